// round 6
// baseline (speedup 1.0000x reference)
#include <cuda_runtime.h>
#include <cstdint>

// Shapes (fixed by the problem)
#define B 8
#define D 256
#define HW (128 * 128)        // 16384
#define C 80
#define NPIX (B * HW)         // 131072
#define RANGE_EXTENDER 10.0f
#define EPS 1e-8f

#define NTHREADS 320          // 16 px-cols x 20 ch-rows
#define PXT 128               // pixels per block (16 cols * 8 px)

typedef unsigned long long u64;

// Duplicated pre-scaled weights: g_w2[d*C + c] = {v, v}, v = w[c][d]/||w_c||*asf[c]*10
// Stored as float2 so each LDG.128 yields two packed duplicated channels.
__device__ float2 g_w2[D * C];

// ---------------------------------------------------------------------------
// Packed fp32x2 helpers
// ---------------------------------------------------------------------------
__device__ __forceinline__ u64 fma2(u64 a, u64 b, u64 c) {
    u64 d;
    asm("fma.rn.f32x2 %0, %1, %2, %3;" : "=l"(d) : "l"(a), "l"(b), "l"(c));
    return d;
}
__device__ __forceinline__ void unpack2(u64 v, float& lo, float& hi) {
    asm("mov.b64 {%0, %1}, %2;" : "=f"(lo), "=f"(hi) : "l"(v));
}

// ---------------------------------------------------------------------------
// Kernel 1: normalize + scale weights, transpose + duplicate to [D][C] pairs
// ---------------------------------------------------------------------------
__global__ void prep_weights_kernel(const float* __restrict__ w,
                                    const float* __restrict__ asf) {
    int c = blockIdx.x;
    int d = threadIdx.x;
    float v = w[c * D + d];

    __shared__ float red[D];
    red[d] = v * v;
    __syncthreads();
    #pragma unroll
    for (int s = D / 2; s > 0; s >>= 1) {
        if (d < s) red[d] += red[d + s];
        __syncthreads();
    }
    float norm = sqrtf(red[0]);
    float scale = asf[c] * RANGE_EXTENDER / fmaxf(norm, EPS);
    float vs = v * scale;
    g_w2[d * C + c] = make_float2(vs, vs);
}

// ---------------------------------------------------------------------------
// Kernel 2: pack-free f32x2 GEMM, no smem staging, no mainloop barriers.
// Thread (px_col 0..15, ch_row 0..19): 8 pixels (4 packed pairs) x 4 channels.
// x pairs come packed from LDG.128; duplicated w pairs come packed from
// LDG.128 on g_w2. Inner loop = 4 LDG.128 + 16 fma2.
// ---------------------------------------------------------------------------
__global__ __launch_bounds__(NTHREADS, 2)
void coshead_main_kernel(const float* __restrict__ x, float* __restrict__ out) {
    __shared__ float norms[PXT];

    const int tid    = threadIdx.x;
    const int px_col = tid & 15;         // 0..15
    const int ch_row = tid >> 4;         // 0..19
    const int px0    = px_col * 8;       // 8 pixels per thread
    const int c0     = ch_row * 4;       // 4 channels per thread

    const int tile    = blockIdx.x;
    const int b       = (tile * PXT) >> 14;
    const int hw_base = (tile * PXT) & (HW - 1);

    const float* xp = x + ((size_t)b * D) * HW + hw_base + px0;
    const float2* wp = g_w2 + c0;        // +k*C per k row

    // acc[ch][px_pair], f32x2 packed over 2 adjacent pixels
    u64 acc[4][4];
    #pragma unroll
    for (int q = 0; q < 4; q++)
        #pragma unroll
        for (int p = 0; p < 4; p++) acc[q][p] = 0ULL;
    u64 n2[4] = {0ULL, 0ULL, 0ULL, 0ULL};   // ch_row 0 only

    #pragma unroll 1
    for (int kt = 0; kt < D; kt += 8) {
        #pragma unroll
        for (int kk = 0; kk < 8; kk++) {
            const int k = kt + kk;
            // 8 pixels = 2 x LDG.128 -> 4 packed pixel-pairs (register pairs)
            ulonglong2 xA = *reinterpret_cast<const ulonglong2*>(
                xp + (size_t)k * HW);
            ulonglong2 xB = *reinterpret_cast<const ulonglong2*>(
                xp + (size_t)k * HW + 4);
            // 4 duplicated channels = 2 x LDG.128 (warp-mostly-uniform, L1)
            ulonglong2 w01 = *reinterpret_cast<const ulonglong2*>(
                wp + (size_t)k * C);
            ulonglong2 w23 = *reinterpret_cast<const ulonglong2*>(
                wp + (size_t)k * C + 2);

            if (ch_row == 0) {
                n2[0] = fma2(xA.x, xA.x, n2[0]);
                n2[1] = fma2(xA.y, xA.y, n2[1]);
                n2[2] = fma2(xB.x, xB.x, n2[2]);
                n2[3] = fma2(xB.y, xB.y, n2[3]);
            }

            acc[0][0] = fma2(xA.x, w01.x, acc[0][0]);
            acc[0][1] = fma2(xA.y, w01.x, acc[0][1]);
            acc[0][2] = fma2(xB.x, w01.x, acc[0][2]);
            acc[0][3] = fma2(xB.y, w01.x, acc[0][3]);
            acc[1][0] = fma2(xA.x, w01.y, acc[1][0]);
            acc[1][1] = fma2(xA.y, w01.y, acc[1][1]);
            acc[1][2] = fma2(xB.x, w01.y, acc[1][2]);
            acc[1][3] = fma2(xB.y, w01.y, acc[1][3]);
            acc[2][0] = fma2(xA.x, w23.x, acc[2][0]);
            acc[2][1] = fma2(xA.y, w23.x, acc[2][1]);
            acc[2][2] = fma2(xB.x, w23.x, acc[2][2]);
            acc[2][3] = fma2(xB.y, w23.x, acc[2][3]);
            acc[3][0] = fma2(xA.x, w23.y, acc[3][0]);
            acc[3][1] = fma2(xA.y, w23.y, acc[3][1]);
            acc[3][2] = fma2(xB.x, w23.y, acc[3][2]);
            acc[3][3] = fma2(xB.y, w23.y, acc[3][3]);
        }
    }

    // ch_row 0 publishes inverse norms for its 8 pixels
    if (ch_row == 0) {
        #pragma unroll
        for (int p = 0; p < 4; p++) {
            float a, bb;
            unpack2(n2[p], a, bb);
            norms[px0 + 2 * p]     = 1.0f / fmaxf(sqrtf(a),  EPS);
            norms[px0 + 2 * p + 1] = 1.0f / fmaxf(sqrtf(bb), EPS);
        }
    }
    __syncthreads();

    float inv[8];
    #pragma unroll
    for (int i = 0; i < 8; i++) inv[i] = norms[px0 + i];

    // out[b][c][hw]: per channel, 8 contiguous pixels -> 2 x STG.128
    float* ob = out + ((size_t)b * C + c0) * HW + hw_base + px0;
    #pragma unroll
    for (int q = 0; q < 4; q++) {
        float v0, v1, v2, v3, v4, v5, v6, v7;
        unpack2(acc[q][0], v0, v1);
        unpack2(acc[q][1], v2, v3);
        unpack2(acc[q][2], v4, v5);
        unpack2(acc[q][3], v6, v7);
        float4 lo = make_float4(v0 * inv[0], v1 * inv[1], v2 * inv[2], v3 * inv[3]);
        float4 hi = make_float4(v4 * inv[4], v5 * inv[5], v6 * inv[6], v7 * inv[7]);
        float* oc = ob + (size_t)q * HW;
        *reinterpret_cast<float4*>(oc)     = lo;
        *reinterpret_cast<float4*>(oc + 4) = hi;
    }
}

// ---------------------------------------------------------------------------
// Launch
// ---------------------------------------------------------------------------
extern "C" void kernel_launch(void* const* d_in, const int* in_sizes, int n_in,
                              void* d_out, int out_size) {
    const float* x   = (const float*)d_in[0];  // [B, D, H, W]
    const float* w   = (const float*)d_in[1];  // [C, D]
    const float* asf = (const float*)d_in[2];  // [C]
    float* out = (float*)d_out;                // [B, C, H, W]

    prep_weights_kernel<<<C, D>>>(w, asf);
    coshead_main_kernel<<<NPIX / PXT, NTHREADS>>>(x, out);
}

// round 8
// speedup vs baseline: 5.8266x; 5.8266x over previous
#include <cuda_runtime.h>
#include <cuda_bf16.h>
#include <cstdint>

#define B 8
#define D 256
#define HW (128 * 128)
#define C 80
#define NPIX (B * HW)
#define RANGE_EXTENDER 10.0f
#define EPS 1e-8f

#define KC 32                 // K per chunk
#define NT (D / KC)           // 8 chunks
#define PXT 128               // pixels per CTA (= M)
#define NTHREADS 256          // 8 warps: 4 px-groups x 2 ch-groups

// smem map (dynamic)
#define S_XH0 0               // 128px * 64B
#define S_XL0 8192
#define S_XH1 16384
#define S_XL1 24576
#define S_W0  32768           // [hl][80c][64B] = 10240
#define S_W1  43008
#define S_NP  53248           // norm partials 2*128*4
#define S_NI  54272           // inv norms 128*4
#define S_TOTAL 54784

// Pre-split, pre-swizzled weight image: [chunk t][hl][c][64B row]
__device__ __align__(16) unsigned char g_wimg[NT * 2 * C * 64];

// ---------------------------------------------------------------------------
// helpers
// ---------------------------------------------------------------------------
__device__ __forceinline__ uint32_t smem_u32(const void* p) {
    return (uint32_t)__cvta_generic_to_shared(p);
}
__device__ __forceinline__ void cp_async16(uint32_t s, const void* g) {
    asm volatile("cp.async.cg.shared.global [%0], [%1], 16;" :: "r"(s), "l"(g) : "memory");
}
__device__ __forceinline__ void cp_commit() {
    asm volatile("cp.async.commit_group;" ::: "memory");
}
template <int N> __device__ __forceinline__ void cp_wait() {
    asm volatile("cp.async.wait_group %0;" :: "n"(N) : "memory");
}

// bank-conflict-free swizzled address within a 64B-row tile (row = px or c)
__device__ __forceinline__ int swz_addr(int row, int chunk, int in) {
    return row * 64 + ((chunk ^ ((row >> 1) & 3)) << 4)
                    + ((in ^ ((row >> 3) & 3)) << 2);
}

// pack two floats -> bf16x2 (lo = first arg)
__device__ __forceinline__ uint32_t cvt_bf16x2(float lo, float hi) {
    uint32_t r;
    asm("cvt.rn.bf16x2.f32 %0, %1, %2;" : "=r"(r) : "f"(hi), "f"(lo));
    return r;
}

__device__ __forceinline__ void mma_bf16(float* d,
                                         uint32_t a0, uint32_t a1, uint32_t a2, uint32_t a3,
                                         uint32_t b0, uint32_t b1) {
    asm volatile(
        "mma.sync.aligned.m16n8k16.row.col.f32.bf16.bf16.f32 "
        "{%0,%1,%2,%3}, {%4,%5,%6,%7}, {%8,%9}, {%0,%1,%2,%3};"
        : "+f"(d[0]), "+f"(d[1]), "+f"(d[2]), "+f"(d[3])
        : "r"(a0), "r"(a1), "r"(a2), "r"(a3), "r"(b0), "r"(b1));
}

// ---------------------------------------------------------------------------
// Kernel 1: normalize+scale weights; bf16 hi/lo split; write swizzled image
// ---------------------------------------------------------------------------
__global__ void prep_weights_kernel(const float* __restrict__ w,
                                    const float* __restrict__ asf) {
    int c = blockIdx.x;
    int d = threadIdx.x;
    float v = w[c * D + d];

    __shared__ float red[D];
    red[d] = v * v;
    __syncthreads();
    #pragma unroll
    for (int s = D / 2; s > 0; s >>= 1) {
        if (d < s) red[d] += red[d + s];
        __syncthreads();
    }
    float scale = asf[c] * RANGE_EXTENDER / fmaxf(sqrtf(red[0]), EPS);
    float wn = v * scale;

    __nv_bfloat16 h = __float2bfloat16(wn);
    float hf = __bfloat162float(h);
    __nv_bfloat16 l = __float2bfloat16(wn - hf);

    int t  = d >> 5;           // chunk
    int kl = d & 31;
    int kp = kl >> 1, chunk = kp >> 2, in = kp & 3;
    int inner = ((chunk ^ ((c >> 1) & 3)) << 4) + ((in ^ ((c >> 3) & 3)) << 2) + (kl & 1) * 2;

    size_t base = ((size_t)(t * 2 + 0) * C + c) * 64 + inner;
    *reinterpret_cast<__nv_bfloat16*>(g_wimg + base) = h;
    base = ((size_t)(t * 2 + 1) * C + c) * 64 + inner;
    *reinterpret_cast<__nv_bfloat16*>(g_wimg + base) = l;
}

// ---------------------------------------------------------------------------
// Kernel 2: bf16 mma.sync GEMM, 3-term split, fused norm.
// ---------------------------------------------------------------------------
__global__ __launch_bounds__(NTHREADS, 2)
void coshead_main_kernel(const float* __restrict__ x, float* __restrict__ out) {
    extern __shared__ char smem[];
    const uint32_t sb = smem_u32(smem);

    const int tid  = threadIdx.x;
    const int lane = tid & 31;
    const int wid  = tid >> 5;
    const int pxbase = (wid & 3) * 32;     // warp px group
    const int chbase = (wid >> 2) * 40;    // warp ch group
    const int r = lane >> 2;
    const int q = lane & 3;

    const int tile    = blockIdx.x;
    const int b       = (tile * PXT) >> 14;
    const int hw_base = (tile * PXT) & (HW - 1);
    const float* xg = x + ((size_t)b * D) * HW + hw_base;

    // conversion role
    const int cpx  = tid & 127;            // pixel
    const int half = tid >> 7;             // k half of chunk
    float n2 = 0.0f;

    // convert x chunk t into buffer buf (exact bf16 hi/lo split + norm accum)
    auto convert_x = [&](int t, int buf) {
        const float* xr = xg + (size_t)(t * KC + half * 16) * HW + cpx;
        char* xh = smem + (buf ? S_XH1 : S_XH0);
        char* xl = smem + (buf ? S_XL1 : S_XL0);
        #pragma unroll
        for (int j = 0; j < 8; j++) {
            float v0 = xr[(size_t)(2 * j) * HW];
            float v1 = xr[(size_t)(2 * j + 1) * HW];
            n2 = fmaf(v0, v0, n2);
            n2 = fmaf(v1, v1, n2);
            __nv_bfloat16 h0 = __float2bfloat16(v0);
            __nv_bfloat16 h1 = __float2bfloat16(v1);
            float l0 = v0 - __bfloat162float(h0);
            float l1 = v1 - __bfloat162float(h1);
            int kp = half * 8 + j;
            int addr = swz_addr(cpx, kp >> 2, kp & 3);
            *reinterpret_cast<uint32_t*>(xh + addr) =
                ((uint32_t)__bfloat16_as_ushort(h1) << 16) | __bfloat16_as_ushort(h0);
            *reinterpret_cast<uint32_t*>(xl + addr) = cvt_bf16x2(l0, l1);
        }
    };

    auto stage_w = [&](int t, int buf) {
        const unsigned char* src = g_wimg + (size_t)t * (2 * C * 64);
        uint32_t dst = sb + (buf ? S_W1 : S_W0);
        #pragma unroll
        for (int i = tid; i < (2 * C * 64) / 16; i += NTHREADS)
            cp_async16(dst + i * 16, src + i * 16);
        cp_commit();
    };

    float acc[2][5][4];
    #pragma unroll
    for (int m = 0; m < 2; m++)
        #pragma unroll
        for (int n = 0; n < 5; n++)
            #pragma unroll
            for (int k = 0; k < 4; k++) acc[m][n][k] = 0.0f;

    convert_x(0, 0);
    stage_w(0, 0);

    for (int t = 0; t < NT; t++) {
        const int buf = t & 1;
        cp_wait<0>();
        __syncthreads();
        if (t + 1 < NT) stage_w(t + 1, buf ^ 1);

        const char* xh = smem + (buf ? S_XH1 : S_XH0);
        const char* xl = smem + (buf ? S_XL1 : S_XL0);
        const char* wh = smem + (buf ? S_W1 : S_W0);
        const char* wl = wh + C * 64;

        #pragma unroll
        for (int s = 0; s < 2; s++) {
            uint32_t ah[2][4], al_[2][4];
            #pragma unroll
            for (int m = 0; m < 2; m++) {
                int p0 = pxbase + m * 16 + r;
                int p1 = p0 + 8;
                int a00 = swz_addr(p0, 2 * s, q);
                int a01 = swz_addr(p1, 2 * s, q);
                int a10 = swz_addr(p0, 2 * s + 1, q);
                int a11 = swz_addr(p1, 2 * s + 1, q);
                ah[m][0] = *reinterpret_cast<const uint32_t*>(xh + a00);
                ah[m][1] = *reinterpret_cast<const uint32_t*>(xh + a01);
                ah[m][2] = *reinterpret_cast<const uint32_t*>(xh + a10);
                ah[m][3] = *reinterpret_cast<const uint32_t*>(xh + a11);
                al_[m][0] = *reinterpret_cast<const uint32_t*>(xl + a00);
                al_[m][1] = *reinterpret_cast<const uint32_t*>(xl + a01);
                al_[m][2] = *reinterpret_cast<const uint32_t*>(xl + a10);
                al_[m][3] = *reinterpret_cast<const uint32_t*>(xl + a11);
            }
            #pragma unroll
            for (int n = 0; n < 5; n++) {
                int cr = chbase + n * 8 + r;
                int b0a = swz_addr(cr, 2 * s, q);
                int b1a = swz_addr(cr, 2 * s + 1, q);
                uint32_t bh0 = *reinterpret_cast<const uint32_t*>(wh + b0a);
                uint32_t bh1 = *reinterpret_cast<const uint32_t*>(wh + b1a);
                uint32_t bl0 = *reinterpret_cast<const uint32_t*>(wl + b0a);
                uint32_t bl1 = *reinterpret_cast<const uint32_t*>(wl + b1a);
                #pragma unroll
                for (int m = 0; m < 2; m++) {
                    mma_bf16(acc[m][n], ah[m][0], ah[m][1], ah[m][2], ah[m][3], bh0, bh1);
                    mma_bf16(acc[m][n], al_[m][0], al_[m][1], al_[m][2], al_[m][3], bh0, bh1);
                    mma_bf16(acc[m][n], ah[m][0], ah[m][1], ah[m][2], ah[m][3], bl0, bl1);
                }
            }
        }

        if (t + 1 < NT) convert_x(t + 1, buf ^ 1);
    }

    // norms: combine two halves, compute inverse
    float* np = reinterpret_cast<float*>(smem + S_NP);
    float* ni = reinterpret_cast<float*>(smem + S_NI);
    np[half * 128 + cpx] = n2;
    __syncthreads();
    if (tid < 128)
        ni[tid] = 1.0f / fmaxf(sqrtf(np[tid] + np[128 + tid]), EPS);
    __syncthreads();

    // epilogue
    float* ob = out + ((size_t)b * C) * HW + hw_base;
    #pragma unroll
    for (int m = 0; m < 2; m++) {
        int p0 = pxbase + m * 16 + r;
        int p1 = p0 + 8;
        float i0 = ni[p0], i1 = ni[p1];
        #pragma unroll
        for (int n = 0; n < 5; n++) {
            int ch = chbase + n * 8 + q * 2;
            ob[(size_t)ch * HW + p0]       = acc[m][n][0] * i0;
            ob[(size_t)(ch + 1) * HW + p0] = acc[m][n][1] * i0;
            ob[(size_t)ch * HW + p1]       = acc[m][n][2] * i1;
            ob[(size_t)(ch + 1) * HW + p1] = acc[m][n][3] * i1;
        }
    }
}

// ---------------------------------------------------------------------------
// Launch
// ---------------------------------------------------------------------------
extern "C" void kernel_launch(void* const* d_in, const int* in_sizes, int n_in,
                              void* d_out, int out_size) {
    const float* x   = (const float*)d_in[0];
    const float* w   = (const float*)d_in[1];
    const float* asf = (const float*)d_in[2];
    float* out = (float*)d_out;

    cudaFuncSetAttribute(coshead_main_kernel,
                         cudaFuncAttributeMaxDynamicSharedMemorySize, S_TOTAL);
    prep_weights_kernel<<<C, D>>>(w, asf);
    coshead_main_kernel<<<NPIX / PXT, NTHREADS, S_TOTAL>>>(x, out);
}

// round 9
// speedup vs baseline: 6.8483x; 1.1753x over previous
#include <cuda_runtime.h>
#include <cuda_bf16.h>
#include <cstdint>

#define B 8
#define D 256
#define HW (128 * 128)
#define C 80
#define NPIX (B * HW)
#define RANGE_EXTENDER 10.0f
#define EPS 1e-8f

#define KC 32                 // K per chunk
#define NT (D / KC)           // 8 chunks
#define PXT 128               // pixels per CTA (= M)
#define NTHREADS 256          // 8 warps: 4 px-groups x 2 ch-groups

// smem map (dynamic)
#define S_XR 0                // raw x: 2 x 16KB
#define S_XS 32768            // swizzled bf16: 2 x (xh 8KB + xl 8KB)
#define S_W  65536            // w image: 2 x 10240 (wh 5120 + wl 5120)
#define S_NP 86016            // norm partials 2*128*4
#define S_NI 87040            // inv norms 128*4
#define S_TOTAL 87552

// Pre-split weight image, 16B-swizzled: [chunk t][hl][c][64B]
__device__ __align__(16) unsigned char g_wimg[NT * 2 * C * 64];

// ---------------------------------------------------------------------------
// helpers
// ---------------------------------------------------------------------------
__device__ __forceinline__ uint32_t smem_u32(const void* p) {
    return (uint32_t)__cvta_generic_to_shared(p);
}
__device__ __forceinline__ void cp_async16(uint32_t s, const void* g) {
    asm volatile("cp.async.cg.shared.global [%0], [%1], 16;" :: "r"(s), "l"(g) : "memory");
}
__device__ __forceinline__ void cp_commit() {
    asm volatile("cp.async.commit_group;" ::: "memory");
}
template <int N> __device__ __forceinline__ void cp_wait() {
    asm volatile("cp.async.wait_group %0;" :: "n"(N) : "memory");
}
__device__ __forceinline__ uint32_t cvt_bf16x2(float lo, float hi) {
    uint32_t r;
    asm("cvt.rn.bf16x2.f32 %0, %1, %2;" : "=r"(r) : "f"(hi), "f"(lo));
    return r;
}
__device__ __forceinline__ void ldsm_x4(uint32_t* r, uint32_t addr) {
    asm volatile("ldmatrix.sync.aligned.m8n8.x4.shared.b16 {%0,%1,%2,%3}, [%4];"
                 : "=r"(r[0]), "=r"(r[1]), "=r"(r[2]), "=r"(r[3]) : "r"(addr));
}
__device__ __forceinline__ void ldsm_x2(uint32_t* r, uint32_t addr) {
    asm volatile("ldmatrix.sync.aligned.m8n8.x2.shared.b16 {%0,%1}, [%2];"
                 : "=r"(r[0]), "=r"(r[1]) : "r"(addr));
}
__device__ __forceinline__ void mma_bf16(float* d, const uint32_t* a,
                                         uint32_t b0, uint32_t b1) {
    asm volatile(
        "mma.sync.aligned.m16n8k16.row.col.f32.bf16.bf16.f32 "
        "{%0,%1,%2,%3}, {%4,%5,%6,%7}, {%8,%9}, {%0,%1,%2,%3};"
        : "+f"(d[0]), "+f"(d[1]), "+f"(d[2]), "+f"(d[3])
        : "r"(a[0]), "r"(a[1]), "r"(a[2]), "r"(a[3]), "r"(b0), "r"(b1));
}

// ---------------------------------------------------------------------------
// Kernel 1: normalize+scale weights; bf16 hi/lo split; 16B-swizzled image
// ---------------------------------------------------------------------------
__global__ void prep_weights_kernel(const float* __restrict__ w,
                                    const float* __restrict__ asf) {
    int c = blockIdx.x;
    int d = threadIdx.x;
    float v = w[c * D + d];

    __shared__ float red[D];
    red[d] = v * v;
    __syncthreads();
    #pragma unroll
    for (int s = D / 2; s > 0; s >>= 1) {
        if (d < s) red[d] += red[d + s];
        __syncthreads();
    }
    float scale = asf[c] * RANGE_EXTENDER / fmaxf(sqrtf(red[0]), EPS);
    float wn = v * scale;

    __nv_bfloat16 h = __float2bfloat16(wn);
    __nv_bfloat16 l = __float2bfloat16(wn - __bfloat162float(h));

    int t  = d >> 5;                 // chunk
    int kl = d & 31;
    int kp = kl >> 1;
    int chunk = kp >> 2;             // 16B chunk within 64B row (0..3)
    int word  = kp & 3;
    int inner = ((chunk ^ ((c >> 1) & 3)) << 4) + (word << 2) + (kl & 1) * 2;

    size_t hb = ((size_t)(t * 2 + 0) * C + c) * 64 + inner;
    size_t lb = ((size_t)(t * 2 + 1) * C + c) * 64 + inner;
    *reinterpret_cast<__nv_bfloat16*>(g_wimg + hb) = h;
    *reinterpret_cast<__nv_bfloat16*>(g_wimg + lb) = l;
}

// ---------------------------------------------------------------------------
// Kernel 2: bf16 mma.sync GEMM, 3-term split, cp.async staged x, ldmatrix frags
// ---------------------------------------------------------------------------
__global__ __launch_bounds__(NTHREADS, 2)
void coshead_main_kernel(const float* __restrict__ x, float* __restrict__ out) {
    extern __shared__ char smem[];
    const uint32_t sb = smem_u32(smem);

    const int tid  = threadIdx.x;
    const int lane = tid & 31;
    const int wid  = tid >> 5;
    const int pxbase = (wid & 3) * 32;
    const int chbase = (wid >> 2) * 40;
    const int r = lane >> 2;
    const int q = lane & 3;

    const int tile    = blockIdx.x;
    const int b       = (tile * PXT) >> 14;
    const int hw_base = (tile * PXT) & (HW - 1);
    const float4* gx4 = reinterpret_cast<const float4*>(
        x + ((size_t)b * D) * HW + hw_base);

    // ---- staging ----
    auto stage = [&](int t, int buf) {
        // x raw: 32 rows x 512B (k-major, px contiguous)
        uint32_t xd = sb + S_XR + buf * 16384;
        #pragma unroll
        for (int i = tid, j = 0; j < 4; j++, i += NTHREADS) {
            int row = i >> 5, col = i & 31;
            cp_async16(xd + row * 512 + col * 16,
                       &gx4[(size_t)(t * KC + row) * (HW / 4) + col]);
        }
        // w image: linear 10240B
        const unsigned char* ws = g_wimg + (size_t)t * 10240;
        uint32_t wd = sb + S_W + buf * 10240;
        for (int i = tid; i < 640; i += NTHREADS)
            cp_async16(wd + i * 16, ws + i * 16);
        cp_commit();
    };

    // ---- conversion role ----
    const int cpx  = tid & 127;
    const int half = tid >> 7;
    float n2 = 0.0f;

    auto convert = [&](int buf) {
        const float* xr = reinterpret_cast<const float*>(smem + S_XR + buf * 16384);
        char* xh = smem + S_XS + buf * 16384;
        char* xl = xh + 8192;
        #pragma unroll
        for (int c2 = 0; c2 < 2; c2++) {
            int chunk = half * 2 + c2;
            uint32_t wh[4], wl[4];
            #pragma unroll
            for (int i = 0; i < 4; i++) {
                int k0 = chunk * 8 + i * 2;
                float v0 = xr[k0 * PXT + cpx];
                float v1 = xr[(k0 + 1) * PXT + cpx];
                n2 = fmaf(v0, v0, n2);
                n2 = fmaf(v1, v1, n2);
                __nv_bfloat16 h0 = __float2bfloat16(v0);
                __nv_bfloat16 h1 = __float2bfloat16(v1);
                float l0 = v0 - __bfloat162float(h0);
                float l1 = v1 - __bfloat162float(h1);
                wh[i] = ((uint32_t)__bfloat16_as_ushort(h1) << 16)
                      | __bfloat16_as_ushort(h0);
                wl[i] = cvt_bf16x2(l0, l1);
            }
            int addr = cpx * 64 + ((chunk ^ ((cpx >> 1) & 3)) << 4);
            *reinterpret_cast<uint4*>(xh + addr) = make_uint4(wh[0], wh[1], wh[2], wh[3]);
            *reinterpret_cast<uint4*>(xl + addr) = make_uint4(wl[0], wl[1], wl[2], wl[3]);
        }
    };

    float acc[2][5][4];
    #pragma unroll
    for (int m = 0; m < 2; m++)
        #pragma unroll
        for (int n = 0; n < 5; n++)
            #pragma unroll
            for (int k = 0; k < 4; k++) acc[m][n][k] = 0.0f;

    stage(0, 0);

    for (int t = 0; t < NT; t++) {
        const int buf = t & 1;
        cp_wait<0>();
        __syncthreads();
        if (t + 1 < NT) stage(t + 1, buf ^ 1);

        convert(buf);
        __syncthreads();

        const uint32_t xhb = sb + S_XS + buf * 16384;
        const uint32_t whb = sb + S_W + buf * 10240;
        const int mat = lane >> 3, rowi = lane & 7;

        #pragma unroll
        for (int s = 0; s < 2; s++) {
            // ---- A fragments (x): 2 m-tiles, hi+lo ----
            uint32_t ah[2][4], al_[2][4];
            #pragma unroll
            for (int m = 0; m < 2; m++) {
                int px = pxbase + m * 16 + ((mat & 1) << 3) + rowi;
                int ck = 2 * s + (mat >> 1);
                uint32_t a = xhb + px * 64 + ((ck ^ ((px >> 1) & 3)) << 4);
                ldsm_x4(ah[m], a);
                ldsm_x4(al_[m], a + 8192);
            }
            // ---- B fragments (w): 5 n-tiles, hi+lo ----
            uint32_t bh[5][2], bl[5][2];
            #pragma unroll
            for (int u = 0; u < 2; u++) {
                int cc = chbase + u * 16 + ((mat >> 1) << 3) + rowi;
                int ck = 2 * s + (mat & 1);
                uint32_t a = whb + cc * 64 + ((ck ^ ((cc >> 1) & 3)) << 4);
                uint32_t rr[4];
                ldsm_x4(rr, a);
                bh[2 * u][0] = rr[0]; bh[2 * u][1] = rr[1];
                bh[2 * u + 1][0] = rr[2]; bh[2 * u + 1][1] = rr[3];
                ldsm_x4(rr, a + 5120);
                bl[2 * u][0] = rr[0]; bl[2 * u][1] = rr[1];
                bl[2 * u + 1][0] = rr[2]; bl[2 * u + 1][1] = rr[3];
            }
            {
                int cc = chbase + 32 + rowi;
                int ck = 2 * s + (mat & 1);
                uint32_t a = whb + cc * 64 + ((ck ^ ((cc >> 1) & 3)) << 4);
                uint32_t rr[2];
                ldsm_x2(rr, a);
                bh[4][0] = rr[0]; bh[4][1] = rr[1];
                ldsm_x2(rr, a + 5120);
                bl[4][0] = rr[0]; bl[4][1] = rr[1];
            }
            // ---- 30 MMAs ----
            #pragma unroll
            for (int n = 0; n < 5; n++)
                #pragma unroll
                for (int m = 0; m < 2; m++) {
                    mma_bf16(acc[m][n], ah[m],  bh[n][0], bh[n][1]);
                    mma_bf16(acc[m][n], al_[m], bh[n][0], bh[n][1]);
                    mma_bf16(acc[m][n], ah[m],  bl[n][0], bl[n][1]);
                }
        }
        __syncthreads();
    }

    // ---- norms ----
    float* np = reinterpret_cast<float*>(smem + S_NP);
    float* ni = reinterpret_cast<float*>(smem + S_NI);
    np[half * 128 + cpx] = n2;
    __syncthreads();
    if (tid < 128)
        ni[tid] = 1.0f / fmaxf(sqrtf(np[tid] + np[128 + tid]), EPS);
    __syncthreads();

    // ---- epilogue ----
    float* ob = out + ((size_t)b * C) * HW + hw_base;
    #pragma unroll
    for (int m = 0; m < 2; m++) {
        int p0 = pxbase + m * 16 + r;
        int p1 = p0 + 8;
        float i0 = ni[p0], i1 = ni[p1];
        #pragma unroll
        for (int n = 0; n < 5; n++) {
            int ch = chbase + n * 8 + q * 2;
            ob[(size_t)ch * HW + p0]       = acc[m][n][0] * i0;
            ob[(size_t)(ch + 1) * HW + p0] = acc[m][n][1] * i0;
            ob[(size_t)ch * HW + p1]       = acc[m][n][2] * i1;
            ob[(size_t)(ch + 1) * HW + p1] = acc[m][n][3] * i1;
        }
    }
}

// ---------------------------------------------------------------------------
// Launch
// ---------------------------------------------------------------------------
extern "C" void kernel_launch(void* const* d_in, const int* in_sizes, int n_in,
                              void* d_out, int out_size) {
    const float* x   = (const float*)d_in[0];
    const float* w   = (const float*)d_in[1];
    const float* asf = (const float*)d_in[2];
    float* out = (float*)d_out;

    cudaFuncSetAttribute(coshead_main_kernel,
                         cudaFuncAttributeMaxDynamicSharedMemorySize, S_TOTAL);
    prep_weights_kernel<<<C, D>>>(w, asf);
    coshead_main_kernel<<<NPIX / PXT, NTHREADS, S_TOTAL>>>(x, out);
}

// round 10
// speedup vs baseline: 7.0369x; 1.0275x over previous
#include <cuda_runtime.h>
#include <cuda_bf16.h>
#include <cstdint>

#define B 8
#define D 256
#define HW (128 * 128)
#define C 80
#define NPIX (B * HW)
#define RANGE_EXTENDER 10.0f
#define EPS 1e-8f

#define KC 32                 // K per chunk
#define NT (D / KC)           // 8 chunks
#define PXT 128               // pixels per CTA (= M)
#define NTHREADS 256          // 8 warps: 4 px-groups x 2 ch-groups

// smem map (dynamic)
#define S_XS 0                // swizzled bf16 x: 2 x (xh 8KB + xl 8KB)
#define S_W  32768            // w image: 2 x 10240 (wh 5120 + wl 5120)
#define S_NP 53248            // norm partials 2*128*4
#define S_NI 54272            // inv norms 128*4
#define S_TOTAL 54784

// Pre-split weight image, 16B-swizzled: [chunk t][hl][c][64B]
__device__ __align__(16) unsigned char g_wimg[NT * 2 * C * 64];

// ---------------------------------------------------------------------------
// helpers
// ---------------------------------------------------------------------------
__device__ __forceinline__ uint32_t smem_u32(const void* p) {
    return (uint32_t)__cvta_generic_to_shared(p);
}
__device__ __forceinline__ void cp_async16(uint32_t s, const void* g) {
    asm volatile("cp.async.cg.shared.global [%0], [%1], 16;" :: "r"(s), "l"(g) : "memory");
}
__device__ __forceinline__ void cp_commit() {
    asm volatile("cp.async.commit_group;" ::: "memory");
}
template <int N> __device__ __forceinline__ void cp_wait() {
    asm volatile("cp.async.wait_group %0;" :: "n"(N) : "memory");
}
__device__ __forceinline__ uint32_t cvt_bf16x2(float lo, float hi) {
    uint32_t r;
    asm("cvt.rn.bf16x2.f32 %0, %1, %2;" : "=r"(r) : "f"(hi), "f"(lo));
    return r;
}
__device__ __forceinline__ void ldsm_x4(uint32_t* r, uint32_t addr) {
    asm volatile("ldmatrix.sync.aligned.m8n8.x4.shared.b16 {%0,%1,%2,%3}, [%4];"
                 : "=r"(r[0]), "=r"(r[1]), "=r"(r[2]), "=r"(r[3]) : "r"(addr));
}
__device__ __forceinline__ void ldsm_x2(uint32_t* r, uint32_t addr) {
    asm volatile("ldmatrix.sync.aligned.m8n8.x2.shared.b16 {%0,%1}, [%2];"
                 : "=r"(r[0]), "=r"(r[1]) : "r"(addr));
}
__device__ __forceinline__ void mma_bf16(float* d, const uint32_t* a,
                                         uint32_t b0, uint32_t b1) {
    asm volatile(
        "mma.sync.aligned.m16n8k16.row.col.f32.bf16.bf16.f32 "
        "{%0,%1,%2,%3}, {%4,%5,%6,%7}, {%8,%9}, {%0,%1,%2,%3};"
        : "+f"(d[0]), "+f"(d[1]), "+f"(d[2]), "+f"(d[3])
        : "r"(a[0]), "r"(a[1]), "r"(a[2]), "r"(a[3]), "r"(b0), "r"(b1));
}

// ---------------------------------------------------------------------------
// Kernel 1: normalize+scale weights; bf16 hi/lo split; 16B-swizzled image
// ---------------------------------------------------------------------------
__global__ void prep_weights_kernel(const float* __restrict__ w,
                                    const float* __restrict__ asf) {
    int c = blockIdx.x;
    int d = threadIdx.x;
    float v = w[c * D + d];

    __shared__ float red[D];
    red[d] = v * v;
    __syncthreads();
    #pragma unroll
    for (int s = D / 2; s > 0; s >>= 1) {
        if (d < s) red[d] += red[d + s];
        __syncthreads();
    }
    float scale = asf[c] * RANGE_EXTENDER / fmaxf(sqrtf(red[0]), EPS);
    float wn = v * scale;

    __nv_bfloat16 h = __float2bfloat16(wn);
    __nv_bfloat16 l = __float2bfloat16(wn - __bfloat162float(h));

    int t  = d >> 5;
    int kl = d & 31;
    int kp = kl >> 1;
    int chunk = kp >> 2;
    int word  = kp & 3;
    int inner = ((chunk ^ ((c >> 1) & 3)) << 4) + (word << 2) + (kl & 1) * 2;

    size_t hb = ((size_t)(t * 2 + 0) * C + c) * 64 + inner;
    size_t lb = ((size_t)(t * 2 + 1) * C + c) * 64 + inner;
    *reinterpret_cast<__nv_bfloat16*>(g_wimg + hb) = h;
    *reinterpret_cast<__nv_bfloat16*>(g_wimg + lb) = l;
}

// ---------------------------------------------------------------------------
// Kernel 2: bf16 mma.sync GEMM, 3-term split, pipelined convert/MMA,
// gmem-direct x loads, one barrier per chunk.
// ---------------------------------------------------------------------------
__global__ __launch_bounds__(NTHREADS, 2)
void coshead_main_kernel(const float* __restrict__ x, float* __restrict__ out) {
    extern __shared__ char smem[];
    const uint32_t sb = smem_u32(smem);

    const int tid  = threadIdx.x;
    const int lane = tid & 31;
    const int wid  = tid >> 5;
    const int pxbase = (wid & 3) * 32;
    const int chbase = (wid >> 2) * 40;
    const int r = lane >> 2;
    const int q = lane & 3;

    const int tile    = blockIdx.x;
    const int b       = (tile * PXT) >> 14;
    const int hw_base = (tile * PXT) & (HW - 1);
    const float* xg = x + ((size_t)b * D) * HW + hw_base;

    // conversion role: thread handles pixel cpx, k-half `half` of each chunk
    const int cpx  = tid & 127;
    const int half = tid >> 7;
    float n2 = 0.0f;

    auto stage_w = [&](int t, int buf) {
        const unsigned char* ws = g_wimg + (size_t)t * 10240;
        uint32_t wd = sb + S_W + buf * 10240;
        #pragma unroll
        for (int i = tid, j = 0; j < 3; j++, i += NTHREADS)
            if (i < 640) cp_async16(wd + i * 16, ws + i * 16);
        cp_commit();
    };

    // convert 16 staged x values (chunk t, this thread's half) into XS[buf]
    auto convert = [&](const float* xv, int buf) {
        char* xh = smem + S_XS + buf * 16384;
        char* xl = xh + 8192;
        #pragma unroll
        for (int c2 = 0; c2 < 2; c2++) {
            int chunk = half * 2 + c2;
            uint32_t wh[4], wl[4];
            #pragma unroll
            for (int i = 0; i < 4; i++) {
                float v0 = xv[c2 * 8 + i * 2];
                float v1 = xv[c2 * 8 + i * 2 + 1];
                n2 = fmaf(v0, v0, n2);
                n2 = fmaf(v1, v1, n2);
                __nv_bfloat16 h0 = __float2bfloat16(v0);
                __nv_bfloat16 h1 = __float2bfloat16(v1);
                float l0 = v0 - __bfloat162float(h0);
                float l1 = v1 - __bfloat162float(h1);
                wh[i] = ((uint32_t)__bfloat16_as_ushort(h1) << 16)
                      | __bfloat16_as_ushort(h0);
                wl[i] = cvt_bf16x2(l0, l1);
            }
            int addr = cpx * 64 + ((chunk ^ ((cpx >> 1) & 3)) << 4);
            *reinterpret_cast<uint4*>(xh + addr) = make_uint4(wh[0], wh[1], wh[2], wh[3]);
            *reinterpret_cast<uint4*>(xl + addr) = make_uint4(wl[0], wl[1], wl[2], wl[3]);
        }
    };

    float acc[2][5][4];
    #pragma unroll
    for (int m = 0; m < 2; m++)
        #pragma unroll
        for (int n = 0; n < 5; n++)
            #pragma unroll
            for (int k = 0; k < 4; k++) acc[m][n][k] = 0.0f;

    // prologue: stage w0 (async), convert chunk 0
    stage_w(0, 0);
    {
        float xv[16];
        const float* xr = xg + (size_t)(half * 16) * HW + cpx;
        #pragma unroll
        for (int j = 0; j < 16; j++) xv[j] = xr[(size_t)j * HW];
        convert(xv, 0);
    }

    for (int t = 0; t < NT; t++) {
        const int buf = t & 1;
        if (t + 1 < NT) { stage_w(t + 1, buf ^ 1); cp_wait<1>(); }
        else           { cp_wait<0>(); }
        __syncthreads();   // XS[buf] converted (prev iter/prologue); W[buf] staged

        // issue next chunk's x loads early — they drain under the MMAs
        float xv[16];
        if (t + 1 < NT) {
            const float* xr = xg + (size_t)((t + 1) * KC + half * 16) * HW + cpx;
            #pragma unroll
            for (int j = 0; j < 16; j++) xv[j] = xr[(size_t)j * HW];
        }

        const uint32_t xhb = sb + S_XS + buf * 16384;
        const uint32_t whb = sb + S_W + buf * 10240;
        const int mat = lane >> 3, rowi = lane & 7;

        #pragma unroll
        for (int s = 0; s < 2; s++) {
            uint32_t ah[2][4], al_[2][4];
            #pragma unroll
            for (int m = 0; m < 2; m++) {
                int px = pxbase + m * 16 + ((mat & 1) << 3) + rowi;
                int ck = 2 * s + (mat >> 1);
                uint32_t a = xhb + px * 64 + ((ck ^ ((px >> 1) & 3)) << 4);
                ldsm_x4(ah[m], a);
                ldsm_x4(al_[m], a + 8192);
            }
            uint32_t bh[5][2], bl[5][2];
            #pragma unroll
            for (int u = 0; u < 2; u++) {
                int cc = chbase + u * 16 + ((mat >> 1) << 3) + rowi;
                int ck = 2 * s + (mat & 1);
                uint32_t a = whb + cc * 64 + ((ck ^ ((cc >> 1) & 3)) << 4);
                uint32_t rr[4];
                ldsm_x4(rr, a);
                bh[2 * u][0] = rr[0]; bh[2 * u][1] = rr[1];
                bh[2 * u + 1][0] = rr[2]; bh[2 * u + 1][1] = rr[3];
                ldsm_x4(rr, a + 5120);
                bl[2 * u][0] = rr[0]; bl[2 * u][1] = rr[1];
                bl[2 * u + 1][0] = rr[2]; bl[2 * u + 1][1] = rr[3];
            }
            {
                int cc = chbase + 32 + rowi;
                int ck = 2 * s + (mat & 1);
                uint32_t a = whb + cc * 64 + ((ck ^ ((cc >> 1) & 3)) << 4);
                uint32_t rr[2];
                ldsm_x2(rr, a);
                bh[4][0] = rr[0]; bh[4][1] = rr[1];
                ldsm_x2(rr, a + 5120);
                bl[4][0] = rr[0]; bl[4][1] = rr[1];
            }
            #pragma unroll
            for (int n = 0; n < 5; n++)
                #pragma unroll
                for (int m = 0; m < 2; m++) {
                    mma_bf16(acc[m][n], ah[m],  bh[n][0], bh[n][1]);
                    mma_bf16(acc[m][n], al_[m], bh[n][0], bh[n][1]);
                    mma_bf16(acc[m][n], ah[m],  bl[n][0], bl[n][1]);
                }
        }

        // convert next chunk into the other buffer (overlaps tensor drain)
        if (t + 1 < NT) convert(xv, buf ^ 1);
        __syncthreads();
    }

    // ---- norms ----
    float* np = reinterpret_cast<float*>(smem + S_NP);
    float* ni = reinterpret_cast<float*>(smem + S_NI);
    np[half * 128 + cpx] = n2;
    __syncthreads();
    if (tid < 128)
        ni[tid] = 1.0f / fmaxf(sqrtf(np[tid] + np[128 + tid]), EPS);
    __syncthreads();

    // ---- epilogue ----
    float* ob = out + ((size_t)b * C) * HW + hw_base;
    #pragma unroll
    for (int m = 0; m < 2; m++) {
        int p0 = pxbase + m * 16 + r;
        int p1 = p0 + 8;
        float i0 = ni[p0], i1 = ni[p1];
        #pragma unroll
        for (int n = 0; n < 5; n++) {
            int ch = chbase + n * 8 + q * 2;
            ob[(size_t)ch * HW + p0]       = acc[m][n][0] * i0;
            ob[(size_t)(ch + 1) * HW + p0] = acc[m][n][1] * i0;
            ob[(size_t)ch * HW + p1]       = acc[m][n][2] * i1;
            ob[(size_t)(ch + 1) * HW + p1] = acc[m][n][3] * i1;
        }
    }
}

// ---------------------------------------------------------------------------
// Launch
// ---------------------------------------------------------------------------
extern "C" void kernel_launch(void* const* d_in, const int* in_sizes, int n_in,
                              void* d_out, int out_size) {
    const float* x   = (const float*)d_in[0];
    const float* w   = (const float*)d_in[1];
    const float* asf = (const float*)d_in[2];
    float* out = (float*)d_out;

    cudaFuncSetAttribute(coshead_main_kernel,
                         cudaFuncAttributeMaxDynamicSharedMemorySize, S_TOTAL);
    prep_weights_kernel<<<C, D>>>(w, asf);
    coshead_main_kernel<<<NPIX / PXT, NTHREADS, S_TOTAL>>>(x, out);
}